// round 13
// baseline (speedup 1.0000x reference)
#include <cuda_runtime.h>
#include <cstdint>

#define DIM 512
#define BATCH 32
#define M_TOTAL 131072            /* 64*64*32 */
#define MTILE 128
#define KC 32                      /* k per chunk */
#define NCHUNK (DIM/KC)            /* 16 */
#define NTHREADS 128
#define A_STRIDE 36                /* words per A smem row: banks (4g+tg)%32 bijective */
#define B_STRIDE 40                /* words per B smem row: banks (8tg+g)%32 bijective */
#define PF_DIST 4                  /* explicit L2 prefetch distance (chunks) */

/* B operand, tf32-RNE: g_scaled[k*32+b] = rna_tf32(L[k]*style[b][k])  (k-major) */
__device__ uint32_t g_scaled[DIM * BATCH];

__global__ void prep_kernel(const float* __restrict__ style, const float* __restrict__ L) {
    int i = blockIdx.x * blockDim.x + threadIdx.x;
    if (i < DIM * BATCH) {
        int k = i >> 5, b = i & 31;
        float v = L[k] * style[b * DIM + k];
        uint32_t bits;
        asm("cvt.rna.tf32.f32 %0, %1;" : "=r"(bits) : "f"(v));
        g_scaled[i] = bits;
    }
}

__device__ __forceinline__ uint32_t smem_u32(const void* p) {
    return (uint32_t)__cvta_generic_to_shared(p);
}
/* A loads: prefetch the full 256B-aligned block -> chunk c pulls chunk c+1's
   row-segment into L2 (row base is 2KB-aligned, so chunks pair within 256B). */
__device__ __forceinline__ void cp16_pf(uint32_t dst, const void* src) {
    asm volatile("cp.async.cg.shared.global.L2::256B [%0], [%1], 16;" :: "r"(dst), "l"(src));
}
__device__ __forceinline__ void cp16(uint32_t dst, const void* src) {
    asm volatile("cp.async.cg.shared.global [%0], [%1], 16;" :: "r"(dst), "l"(src));
}
__device__ __forceinline__ void cp_commit() {
    asm volatile("cp.async.commit_group;" ::: "memory");
}
__device__ __forceinline__ void cp_wait1() {
    asm volatile("cp.async.wait_group 1;" ::: "memory");
}
__device__ __forceinline__ void l2_prefetch(const void* p) {
    asm volatile("prefetch.global.L2 [%0];" :: "l"(p));
}
__device__ __forceinline__ void st_cs(float* p, float v) {
    asm volatile("st.global.cs.f32 [%0], %1;" :: "l"(p), "f"(v) : "memory");
}
__device__ __forceinline__ void mma_tf32(float* d, const uint32_t* a, uint32_t b0, uint32_t b1) {
    asm volatile(
        "mma.sync.aligned.m16n8k8.row.col.f32.tf32.tf32.f32 "
        "{%0,%1,%2,%3}, {%4,%5,%6,%7}, {%8,%9}, {%0,%1,%2,%3};"
        : "+f"(d[0]), "+f"(d[1]), "+f"(d[2]), "+f"(d[3])
        : "r"(a[0]), "r"(a[1]), "r"(a[2]), "r"(a[3]), "r"(b0), "r"(b1));
}

__global__ void __launch_bounds__(NTHREADS, 4)
gemm_kernel(const float* __restrict__ U, const float* __restrict__ mu, float* __restrict__ out)
{
    __shared__ uint32_t sA[2][MTILE * A_STRIDE];   /* 2 x 18 KB, padded rows */
    __shared__ uint32_t sB[2][KC * B_STRIDE];      /* 2 x  5 KB, padded rows */

    const int tid = threadIdx.x;
    const int wid = tid >> 5;
    const int lid = tid & 31;
    const int g   = lid >> 2;      /* groupID 0..7 */
    const int tg  = lid & 3;       /* thread-in-group 0..3 */
    const int mbase = blockIdx.x * MTILE;

    /* thread tid owns row tid's 128B line for explicit L2 prefetch */
    const float* const myrow = U + (size_t)(mbase + tid) * DIM;

    auto prefetch = [&](int c, int buf) {
        /* A: 128 rows x 128B, coalesced 16B lanes, L2::256B prefetch */
        const float* ubase = U + (size_t)mbase * DIM + c * KC;
        uint32_t adst = smem_u32(&sA[buf][0]);
        #pragma unroll
        for (int j = 0; j < 8; ++j) {
            int id  = j * NTHREADS + tid;
            int row = id >> 3, seg = id & 7;
            cp16_pf(adst + (uint32_t)(row * (A_STRIDE * 4) + seg * 16),
                    ubase + (size_t)row * DIM + seg * 4);
        }
        /* B: 32 k-rows x 128B, padded rows */
        const uint32_t* bsrc = g_scaled + c * KC * BATCH;
        uint32_t bdst = smem_u32(&sB[buf][0]);
        #pragma unroll
        for (int j = 0; j < 2; ++j) {
            int id  = j * NTHREADS + tid;
            int row = id >> 3, seg = id & 7;
            cp16(bdst + (uint32_t)(row * (B_STRIDE * 4) + seg * 16),
                 bsrc + (size_t)row * BATCH + seg * 4);
        }
    };

    float acc[2][4][4];
    #pragma unroll
    for (int mt = 0; mt < 2; ++mt)
        #pragma unroll
        for (int nt = 0; nt < 4; ++nt)
            #pragma unroll
            for (int r = 0; r < 4; ++r) acc[mt][nt][r] = 0.0f;

    prefetch(0, 0); cp_commit();
    prefetch(1, 1); cp_commit();
    /* prologue L2 prefetch: chunks 2..3 (cp.async horizon covers 0..1) */
    l2_prefetch(myrow + 2 * KC);
    l2_prefetch(myrow + 3 * KC);

    for (int c = 0; c < NCHUNK; ++c) {
        cp_wait1();
        __syncthreads();

        /* deep L2 prefetch: one 128B line per thread for chunk c+PF_DIST */
        if (c + PF_DIST < NCHUNK) l2_prefetch(myrow + (c + PF_DIST) * KC);

        const uint32_t* A = sA[c & 1];
        const uint32_t* B = sB[c & 1];

        #pragma unroll
        for (int ks = 0; ks < 4; ++ks) {
            uint32_t a[2][4], b[4][2];
            #pragma unroll
            for (int mt = 0; mt < 2; ++mt) {
                int rb = wid * 32 + mt * 16;
                /* +0x1000: RNE into tf32 (HW truncates low 13 bits) */
                a[mt][0] = A[(rb + g)     * A_STRIDE + ks * 8 + tg]     + 0x1000u;
                a[mt][1] = A[(rb + g + 8) * A_STRIDE + ks * 8 + tg]     + 0x1000u;
                a[mt][2] = A[(rb + g)     * A_STRIDE + ks * 8 + tg + 4] + 0x1000u;
                a[mt][3] = A[(rb + g + 8) * A_STRIDE + ks * 8 + tg + 4] + 0x1000u;
            }
            #pragma unroll
            for (int nt = 0; nt < 4; ++nt) {
                b[nt][0] = B[(ks * 8 + tg)     * B_STRIDE + nt * 8 + g];
                b[nt][1] = B[(ks * 8 + tg + 4) * B_STRIDE + nt * 8 + g];
            }
            #pragma unroll
            for (int mt = 0; mt < 2; ++mt)
                #pragma unroll
                for (int nt = 0; nt < 4; ++nt)
                    mma_tf32(acc[mt][nt], a[mt], b[nt][0], b[nt][1]);
        }

        __syncthreads();
        if (c + 2 < NCHUNK) prefetch(c + 2, c & 1);
        cp_commit();   /* possibly-empty group keeps wait_group accounting simple */
    }

    /* epilogue: add mu, store out[b][m] with evict-first (write-once data) */
    #pragma unroll
    for (int mt = 0; mt < 2; ++mt) {
        int m0 = mbase + wid * 32 + mt * 16 + g;
        float mu0 = __ldg(&mu[m0]);
        float mu1 = __ldg(&mu[m0 + 8]);
        #pragma unroll
        for (int nt = 0; nt < 4; ++nt) {
            int b0 = nt * 8 + 2 * tg;
            st_cs(&out[(size_t)b0       * M_TOTAL + m0],     acc[mt][nt][0] + mu0);
            st_cs(&out[(size_t)(b0 + 1) * M_TOTAL + m0],     acc[mt][nt][1] + mu0);
            st_cs(&out[(size_t)b0       * M_TOTAL + m0 + 8], acc[mt][nt][2] + mu1);
            st_cs(&out[(size_t)(b0 + 1) * M_TOTAL + m0 + 8], acc[mt][nt][3] + mu1);
        }
    }
}

extern "C" void kernel_launch(void* const* d_in, const int* in_sizes, int n_in,
                              void* d_out, int out_size) {
    const float *style = nullptr, *U = nullptr, *L = nullptr, *mu = nullptr;
    for (int i = 0; i < n_in; ++i) {
        switch (in_sizes[i]) {
            case BATCH * DIM:   style = (const float*)d_in[i]; break;
            case M_TOTAL * DIM: U     = (const float*)d_in[i]; break;
            case DIM:           L     = (const float*)d_in[i]; break;
            case M_TOTAL:      mu    = (const float*)d_in[i]; break;
            default: break;
        }
    }
    float* out = (float*)d_out;

    prep_kernel<<<(DIM * BATCH + 255) / 256, 256>>>(style, L);
    gemm_kernel<<<M_TOTAL / MTILE, NTHREADS>>>(U, mu, out);
}

// round 14
// speedup vs baseline: 1.0848x; 1.0848x over previous
#include <cuda_runtime.h>
#include <cstdint>

#define DIM 512
#define BATCH 32
#define M_TOTAL 131072            /* 64*64*32 */
#define MTILE 128
#define KC 32                      /* k per chunk */
#define NCHUNK (DIM/KC)            /* 16 */
#define NTHREADS 128
#define A_STRIDE 36                /* words per A smem row: banks (4g+tg)%32 bijective */
#define B_STRIDE 40                /* words per B smem row: banks (8tg+g)%32 bijective */

/* B operand, tf32-RNE: g_scaled[k*32+b] = rna_tf32(L[k]*style[b][k])  (k-major) */
__device__ uint32_t g_scaled[DIM * BATCH];

__global__ void prep_kernel(const float* __restrict__ style, const float* __restrict__ L) {
    int i = blockIdx.x * blockDim.x + threadIdx.x;
    if (i < DIM * BATCH) {
        int k = i >> 5, b = i & 31;
        float v = L[k] * style[b * DIM + k];
        uint32_t bits;
        asm("cvt.rna.tf32.f32 %0, %1;" : "=r"(bits) : "f"(v));
        g_scaled[i] = bits;
    }
}

__device__ __forceinline__ uint32_t smem_u32(const void* p) {
    return (uint32_t)__cvta_generic_to_shared(p);
}
/* A loads: prefetch the full 256B-aligned block -> the first-processed chunk of
   each pair pulls its partner's row-segment into L2 (row base is 2KB-aligned). */
__device__ __forceinline__ void cp16_pf(uint32_t dst, const void* src) {
    asm volatile("cp.async.cg.shared.global.L2::256B [%0], [%1], 16;" :: "r"(dst), "l"(src));
}
__device__ __forceinline__ void cp16(uint32_t dst, const void* src) {
    asm volatile("cp.async.cg.shared.global [%0], [%1], 16;" :: "r"(dst), "l"(src));
}
__device__ __forceinline__ void cp_commit() {
    asm volatile("cp.async.commit_group;" ::: "memory");
}
__device__ __forceinline__ void cp_wait1() {
    asm volatile("cp.async.wait_group 1;" ::: "memory");
}
__device__ __forceinline__ void st_cs(float* p, float v) {
    asm volatile("st.global.cs.f32 [%0], %1;" :: "l"(p), "f"(v) : "memory");
}
__device__ __forceinline__ void mma_tf32(float* d, const uint32_t* a, uint32_t b0, uint32_t b1) {
    asm volatile(
        "mma.sync.aligned.m16n8k8.row.col.f32.tf32.tf32.f32 "
        "{%0,%1,%2,%3}, {%4,%5,%6,%7}, {%8,%9}, {%0,%1,%2,%3};"
        : "+f"(d[0]), "+f"(d[1]), "+f"(d[2]), "+f"(d[3])
        : "r"(a[0]), "r"(a[1]), "r"(a[2]), "r"(a[3]), "r"(b0), "r"(b1));
}

__global__ void __launch_bounds__(NTHREADS, 4)
gemm_kernel(const float* __restrict__ U, const float* __restrict__ mu, float* __restrict__ out)
{
    __shared__ uint32_t sA[2][MTILE * A_STRIDE];   /* 2 x 18 KB, padded rows */
    __shared__ uint32_t sB[2][KC * B_STRIDE];      /* 2 x  5 KB, padded rows */

    const int tid = threadIdx.x;
    const int wid = tid >> 5;
    const int lid = tid & 31;
    const int g   = lid >> 2;      /* groupID 0..7 */
    const int tg  = lid & 3;       /* thread-in-group 0..3 */
    const int mbase = blockIdx.x * MTILE;
    /* parity stagger: odd CTAs walk chunk pairs swapped (1,0,3,2,...) so their
       256B DRAM fetches land in the opposite half-period -> smoother DRAM stream */
    const int flip = blockIdx.x & 1;

    auto prefetch = [&](int c, int buf) {
        /* A: 128 rows x 128B, coalesced 16B lanes, L2::256B prefetch */
        const float* ubase = U + (size_t)mbase * DIM + c * KC;
        uint32_t adst = smem_u32(&sA[buf][0]);
        #pragma unroll
        for (int j = 0; j < 8; ++j) {
            int id  = j * NTHREADS + tid;
            int row = id >> 3, seg = id & 7;
            cp16_pf(adst + (uint32_t)(row * (A_STRIDE * 4) + seg * 16),
                    ubase + (size_t)row * DIM + seg * 4);
        }
        /* B: 32 k-rows x 128B, padded rows */
        const uint32_t* bsrc = g_scaled + c * KC * BATCH;
        uint32_t bdst = smem_u32(&sB[buf][0]);
        #pragma unroll
        for (int j = 0; j < 2; ++j) {
            int id  = j * NTHREADS + tid;
            int row = id >> 3, seg = id & 7;
            cp16(bdst + (uint32_t)(row * (B_STRIDE * 4) + seg * 16),
                 bsrc + (size_t)row * BATCH + seg * 4);
        }
    };

    float acc[2][4][4];
    #pragma unroll
    for (int mt = 0; mt < 2; ++mt)
        #pragma unroll
        for (int nt = 0; nt < 4; ++nt)
            #pragma unroll
            for (int r = 0; r < 4; ++r) acc[mt][nt][r] = 0.0f;

    prefetch(0 ^ flip, 0); cp_commit();
    prefetch(1 ^ flip, 1); cp_commit();

    for (int i = 0; i < NCHUNK; ++i) {
        const int c = i ^ flip;     /* chunk processed this iteration */
        cp_wait1();
        __syncthreads();
        const uint32_t* A = sA[i & 1];
        const uint32_t* B = sB[i & 1];

        #pragma unroll
        for (int ks = 0; ks < 4; ++ks) {
            uint32_t a[2][4], b[4][2];
            #pragma unroll
            for (int mt = 0; mt < 2; ++mt) {
                int rb = wid * 32 + mt * 16;
                /* +0x1000: RNE into tf32 (HW truncates low 13 bits) */
                a[mt][0] = A[(rb + g)     * A_STRIDE + ks * 8 + tg]     + 0x1000u;
                a[mt][1] = A[(rb + g + 8) * A_STRIDE + ks * 8 + tg]     + 0x1000u;
                a[mt][2] = A[(rb + g)     * A_STRIDE + ks * 8 + tg + 4] + 0x1000u;
                a[mt][3] = A[(rb + g + 8) * A_STRIDE + ks * 8 + tg + 4] + 0x1000u;
            }
            #pragma unroll
            for (int nt = 0; nt < 4; ++nt) {
                b[nt][0] = B[(ks * 8 + tg)     * B_STRIDE + nt * 8 + g];
                b[nt][1] = B[(ks * 8 + tg + 4) * B_STRIDE + nt * 8 + g];
            }
            #pragma unroll
            for (int mt = 0; mt < 2; ++mt)
                #pragma unroll
                for (int nt = 0; nt < 4; ++nt)
                    mma_tf32(acc[mt][nt], a[mt], b[nt][0], b[nt][1]);
        }

        __syncthreads();
        if (i + 2 < NCHUNK) prefetch((i + 2) ^ flip, i & 1);
        cp_commit();   /* possibly-empty group keeps wait_group accounting simple */
    }

    /* epilogue: add mu, store out[b][m] with evict-first (write-once data) */
    #pragma unroll
    for (int mt = 0; mt < 2; ++mt) {
        int m0 = mbase + wid * 32 + mt * 16 + g;
        float mu0 = __ldg(&mu[m0]);
        float mu1 = __ldg(&mu[m0 + 8]);
        #pragma unroll
        for (int nt = 0; nt < 4; ++nt) {
            int b0 = nt * 8 + 2 * tg;
            st_cs(&out[(size_t)b0       * M_TOTAL + m0],     acc[mt][nt][0] + mu0);
            st_cs(&out[(size_t)(b0 + 1) * M_TOTAL + m0],     acc[mt][nt][1] + mu0);
            st_cs(&out[(size_t)b0       * M_TOTAL + m0 + 8], acc[mt][nt][2] + mu1);
            st_cs(&out[(size_t)(b0 + 1) * M_TOTAL + m0 + 8], acc[mt][nt][3] + mu1);
        }
    }
}

extern "C" void kernel_launch(void* const* d_in, const int* in_sizes, int n_in,
                              void* d_out, int out_size) {
    const float *style = nullptr, *U = nullptr, *L = nullptr, *mu = nullptr;
    for (int i = 0; i < n_in; ++i) {
        switch (in_sizes[i]) {
            case BATCH * DIM:   style = (const float*)d_in[i]; break;
            case M_TOTAL * DIM: U     = (const float*)d_in[i]; break;
            case DIM:           L     = (const float*)d_in[i]; break;
            case M_TOTAL:       mu    = (const float*)d_in[i]; break;
            default: break;
        }
    }
    float* out = (float*)d_out;

    prep_kernel<<<(DIM * BATCH + 255) / 256, 256>>>(style, L);
    gemm_kernel<<<M_TOTAL / MTILE, NTHREADS>>>(U, mu, out);
}

// round 15
// speedup vs baseline: 1.1096x; 1.0228x over previous
#include <cuda_runtime.h>
#include <cstdint>

#define DIM 512
#define BATCH 32
#define M_TOTAL 131072            /* 64*64*32 */
#define MTILE 128
#define NTILES (M_TOTAL/MTILE)     /* 1024 */
#define KC 32                      /* k per chunk */
#define NCHUNK (DIM/KC)            /* 16 */
#define NTHREADS 128
#define GRID 592                   /* 148 SMs x 4 CTAs: exactly one wave, persistent */
#define A_STRIDE 36                /* words per A smem row: banks (4g+tg)%32 bijective */
#define B_STRIDE 40                /* words per B smem row: banks (8tg+g)%32 bijective */

/* B operand, tf32-RNE: g_scaled[k*32+b] = rna_tf32(L[k]*style[b][k])  (k-major) */
__device__ uint32_t g_scaled[DIM * BATCH];

__global__ void prep_kernel(const float* __restrict__ style, const float* __restrict__ L) {
    int i = blockIdx.x * blockDim.x + threadIdx.x;
    if (i < DIM * BATCH) {
        int k = i >> 5, b = i & 31;
        float v = L[k] * style[b * DIM + k];
        uint32_t bits;
        asm("cvt.rna.tf32.f32 %0, %1;" : "=r"(bits) : "f"(v));
        g_scaled[i] = bits;
    }
}

__device__ __forceinline__ uint32_t smem_u32(const void* p) {
    return (uint32_t)__cvta_generic_to_shared(p);
}
/* A loads: prefetch the full 256B-aligned block -> chunk c pulls chunk c+1's
   row-segment into L2 (row base is 2KB-aligned, so chunks pair within 256B). */
__device__ __forceinline__ void cp16_pf(uint32_t dst, const void* src) {
    asm volatile("cp.async.cg.shared.global.L2::256B [%0], [%1], 16;" :: "r"(dst), "l"(src));
}
__device__ __forceinline__ void cp16(uint32_t dst, const void* src) {
    asm volatile("cp.async.cg.shared.global [%0], [%1], 16;" :: "r"(dst), "l"(src));
}
__device__ __forceinline__ void cp_commit() {
    asm volatile("cp.async.commit_group;" ::: "memory");
}
__device__ __forceinline__ void cp_wait1() {
    asm volatile("cp.async.wait_group 1;" ::: "memory");
}
__device__ __forceinline__ void st_cs(float* p, float v) {
    asm volatile("st.global.cs.f32 [%0], %1;" :: "l"(p), "f"(v) : "memory");
}
__device__ __forceinline__ void mma_tf32(float* d, const uint32_t* a, uint32_t b0, uint32_t b1) {
    asm volatile(
        "mma.sync.aligned.m16n8k8.row.col.f32.tf32.tf32.f32 "
        "{%0,%1,%2,%3}, {%4,%5,%6,%7}, {%8,%9}, {%0,%1,%2,%3};"
        : "+f"(d[0]), "+f"(d[1]), "+f"(d[2]), "+f"(d[3])
        : "r"(a[0]), "r"(a[1]), "r"(a[2]), "r"(a[3]), "r"(b0), "r"(b1));
}

__global__ void __launch_bounds__(NTHREADS, 4)
gemm_kernel(const float* __restrict__ U, const float* __restrict__ mu, float* __restrict__ out)
{
    __shared__ uint32_t sA[2][MTILE * A_STRIDE];   /* 2 x 18 KB, padded rows */
    __shared__ uint32_t sB[2][KC * B_STRIDE];      /* 2 x  5 KB, padded rows */

    const int tid = threadIdx.x;
    const int wid = tid >> 5;
    const int lid = tid & 31;
    const int g   = lid >> 2;      /* groupID 0..7 */
    const int tg  = lid & 3;       /* thread-in-group 0..3 */

    /* persistent: this CTA owns tiles blockIdx.x and blockIdx.x+GRID */
    const int t0 = blockIdx.x;
    const int nt_own = (t0 + GRID < NTILES) ? 2 : 1;
    const int NQ = nt_own * NCHUNK;     /* global chunk count for this CTA */

    /* global chunk q -> (tile mbase, chunk c) */
    auto qtile = [&](int q) { return ((q >> 4) ? t0 + GRID : t0) * MTILE; };

    auto prefetch = [&](int q, int buf) {
        const int c = q & 15;
        /* A: 128 rows x 128B, coalesced 16B lanes, L2::256B prefetch */
        const float* ubase = U + (size_t)qtile(q) * DIM + c * KC;
        uint32_t adst = smem_u32(&sA[buf][0]);
        #pragma unroll
        for (int j = 0; j < 8; ++j) {
            int id  = j * NTHREADS + tid;
            int row = id >> 3, seg = id & 7;
            cp16_pf(adst + (uint32_t)(row * (A_STRIDE * 4) + seg * 16),
                    ubase + (size_t)row * DIM + seg * 4);
        }
        /* B: 32 k-rows x 128B, padded rows */
        const uint32_t* bsrc = g_scaled + c * KC * BATCH;
        uint32_t bdst = smem_u32(&sB[buf][0]);
        #pragma unroll
        for (int j = 0; j < 2; ++j) {
            int id  = j * NTHREADS + tid;
            int row = id >> 3, seg = id & 7;
            cp16(bdst + (uint32_t)(row * (B_STRIDE * 4) + seg * 16),
                 bsrc + (size_t)row * BATCH + seg * 4);
        }
    };

    float acc[2][4][4];
    #pragma unroll
    for (int mt = 0; mt < 2; ++mt)
        #pragma unroll
        for (int nt = 0; nt < 4; ++nt)
            #pragma unroll
            for (int r = 0; r < 4; ++r) acc[mt][nt][r] = 0.0f;

    prefetch(0, 0); cp_commit();
    prefetch(1, 1); cp_commit();

    for (int q = 0; q < NQ; ++q) {
        cp_wait1();
        __syncthreads();
        const uint32_t* A = sA[q & 1];
        const uint32_t* B = sB[q & 1];

        #pragma unroll
        for (int ks = 0; ks < 4; ++ks) {
            uint32_t a[2][4], b[4][2];
            #pragma unroll
            for (int mt = 0; mt < 2; ++mt) {
                int rb = wid * 32 + mt * 16;
                /* +0x1000: RNE into tf32 (HW truncates low 13 bits) */
                a[mt][0] = A[(rb + g)     * A_STRIDE + ks * 8 + tg]     + 0x1000u;
                a[mt][1] = A[(rb + g + 8) * A_STRIDE + ks * 8 + tg]     + 0x1000u;
                a[mt][2] = A[(rb + g)     * A_STRIDE + ks * 8 + tg + 4] + 0x1000u;
                a[mt][3] = A[(rb + g + 8) * A_STRIDE + ks * 8 + tg + 4] + 0x1000u;
            }
            #pragma unroll
            for (int nt = 0; nt < 4; ++nt) {
                b[nt][0] = B[(ks * 8 + tg)     * B_STRIDE + nt * 8 + g];
                b[nt][1] = B[(ks * 8 + tg + 4) * B_STRIDE + nt * 8 + g];
            }
            #pragma unroll
            for (int mt = 0; mt < 2; ++mt)
                #pragma unroll
                for (int nt = 0; nt < 4; ++nt)
                    mma_tf32(acc[mt][nt], a[mt], b[nt][0], b[nt][1]);
        }

        __syncthreads();
        if (q + 2 < NQ) prefetch(q + 2, q & 1);   /* crosses tile boundary seamlessly */
        cp_commit();   /* possibly-empty group keeps wait_group accounting simple */

        /* end of a tile: epilogue overlaps the already-issued next-tile loads */
        if ((q & 15) == 15) {
            const int mb = qtile(q);
            #pragma unroll
            for (int mt = 0; mt < 2; ++mt) {
                int m0 = mb + wid * 32 + mt * 16 + g;
                float mu0 = __ldg(&mu[m0]);
                float mu1 = __ldg(&mu[m0 + 8]);
                #pragma unroll
                for (int nt = 0; nt < 4; ++nt) {
                    int b0 = nt * 8 + 2 * tg;
                    st_cs(&out[(size_t)b0       * M_TOTAL + m0],     acc[mt][nt][0] + mu0);
                    st_cs(&out[(size_t)(b0 + 1) * M_TOTAL + m0],     acc[mt][nt][1] + mu0);
                    st_cs(&out[(size_t)b0       * M_TOTAL + m0 + 8], acc[mt][nt][2] + mu1);
                    st_cs(&out[(size_t)(b0 + 1) * M_TOTAL + m0 + 8], acc[mt][nt][3] + mu1);
                    #pragma unroll
                    for (int r = 0; r < 4; ++r) acc[mt][nt][r] = 0.0f;
                }
            }
        }
    }
}

extern "C" void kernel_launch(void* const* d_in, const int* in_sizes, int n_in,
                              void* d_out, int out_size) {
    const float *style = nullptr, *U = nullptr, *L = nullptr, *mu = nullptr;
    for (int i = 0; i < n_in; ++i) {
        switch (in_sizes[i]) {
            case BATCH * DIM:   style = (const float*)d_in[i]; break;
            case M_TOTAL * DIM: U     = (const float*)d_in[i]; break;
            case DIM:           L     = (const float*)d_in[i]; break;
            case M_TOTAL:       mu    = (const float*)d_in[i]; break;
            default: break;
        }
    }
    float* out = (float*)d_out;

    prep_kernel<<<(DIM * BATCH + 255) / 256, 256>>>(style, L);
    gemm_kernel<<<GRID, NTHREADS>>>(U, mu, out);
}